// round 13
// baseline (speedup 1.0000x reference)
#include <cuda_runtime.h>

// Kannala-Brandt fisheye round-trip — single-full-wave persistent kernel.
//
// Math (validated R8-R12, rel_err 6.2e-6 vs 1e-3 tolerance):
//   ru = |(px-cx)/fx, (py-cy)/fy|      (sqrt via MUFU.RSQ: ru = q*rsqrt(q))
//   t:  2 fixed-point steps of t <- t - (t*d(t) - ru)
//   out = sinc(t)*(pixel-center) + center   (deg-8 Taylor sinc;
//        d(t)*sin(t)/ru == sin(t)/t at the fixed point, focal lengths cancel)
//
// R12 -> R13: grid 2048 CTAs made wave 2 only 73% full (occ 75%). Now exactly
// one resident wave: 148 SMs x 8 CTAs x 256 thr (regs pinned <=32 via
// launch_bounds), 7 unrolled grid-stride iterations per thread with a depth-2
// rolling prefetch; only the last iteration is bounds-predicated (~3% lanes).

#define CX 640.0f
#define CY 480.0f

#define PBLOCKS (148 * 8)            // one full resident wave
#define PTHREADS 256

struct KParams { float k0, k1, k2, k3, k4, rfx, rfy; };

__device__ __forceinline__ KParams load_params(const float* kvec,
                                               const float* fx_p,
                                               const float* fy_p)
{
    KParams P;
    P.k0 = __ldg(&kvec[0]); P.k1 = __ldg(&kvec[1]); P.k2 = __ldg(&kvec[2]);
    P.k3 = __ldg(&kvec[3]); P.k4 = __ldg(&kvec[4]);
    P.rfx = __fdividef(1.0f, __ldg(fx_p));
    P.rfy = __fdividef(1.0f, __ldg(fy_p));
    return P;
}

__device__ __forceinline__ float2 kb_point(float px, float py, const KParams& P)
{
    float dx = px - CX;
    float dy = py - CY;
    float mx = dx * P.rfx;
    float my = dy * P.rfy;
    float q  = fmaf(mx, mx, fmaf(my, my, 1e-30f));
    float ru = q * rsqrtf(q);

    float t = ru;
#pragma unroll
    for (int it = 0; it < 2; ++it) {
        float p = ((((P.k4 * t + P.k3) * t + P.k2) * t + P.k1) * t + P.k0);
        float r = fmaf(p, t, -ru);
        t = t - r;
    }

    float t2 = t * t;
    float w = fmaf(t2, fmaf(t2, fmaf(t2, fmaf(t2, 2.7557319e-6f, -1.9841270e-4f),
                                     8.3333333e-3f), -1.6666667e-1f), 1.0f);

    return make_float2(fmaf(w, dx, CX), fmaf(w, dy, CY));
}

// Persistent kernel: requires (ITERS-1)*gridDim*blockDim <= n_pairs
//                          <= ITERS*gridDim*blockDim.
// Iterations 0..ITERS-2 need no bounds check; only the last is predicated.
template <int ITERS>
__global__ void __launch_bounds__(PTHREADS, 8)
kb_persist_kernel(const float4* __restrict__ in4,
                  const float*  __restrict__ kvec,
                  const float*  __restrict__ fx_p,
                  const float*  __restrict__ fy_p,
                  float4*       __restrict__ out4,
                  int n_pairs)
{
    const int T  = gridDim.x * PTHREADS;
    const int i0 = blockIdx.x * PTHREADS + threadIdx.x;
    const KParams P = load_params(kvec, fx_p, fy_p);

    // depth-2 rolling prefetch (iters 0..ITERS-2 provably in range)
    float4 b0 = in4[i0];
    float4 b1 = in4[i0 + T];

#pragma unroll
    for (int k = 0; k < ITERS; ++k) {
        float4 nxt = make_float4(0.f, 0.f, 0.f, 0.f);
        if (k + 2 <= ITERS - 2) {                 // compile-time: always valid
            nxt = in4[i0 + (k + 2) * T];
        } else if (k + 2 == ITERS - 1) {          // compile-time: last iter load
            int il = i0 + (k + 2) * T;
            if (il < n_pairs) nxt = in4[il];
        }

        int icur = i0 + k * T;
        if (k < ITERS - 1 || icur < n_pairs) {
            float2 a = kb_point(b0.x, b0.y, P);
            float2 b = kb_point(b0.z, b0.w, P);
            out4[icur] = make_float4(a.x, a.y, b.x, b.y);
        }
        b0 = b1; b1 = nxt;
    }
}

// ---- generic fallback ----
__global__ void __launch_bounds__(256)
kb_generic_kernel(const float4* __restrict__ in4,
                  const float2* __restrict__ in2,
                  const float*  __restrict__ kvec,
                  const float*  __restrict__ fx_p,
                  const float*  __restrict__ fy_p,
                  float4*       __restrict__ out4,
                  float2*       __restrict__ out2,
                  int n_pairs, int n_tail_pts)
{
    const int stride = gridDim.x * blockDim.x;
    int i = blockIdx.x * blockDim.x + threadIdx.x;
    const KParams P = load_params(kvec, fx_p, fy_p);

    for (; i < n_pairs; i += stride) {
        float4 p = in4[i];
        float2 a = kb_point(p.x, p.y, P);
        float2 b = kb_point(p.z, p.w, P);
        out4[i] = make_float4(a.x, a.y, b.x, b.y);
    }

    if (n_tail_pts && blockIdx.x == 0 && threadIdx.x == 0) {
        for (int j = 0; j < n_tail_pts; ++j) {
            int idx = 2 * n_pairs + j;
            float2 p = in2[idx];
            out2[idx] = kb_point(p.x, p.y, P);
        }
    }
}

extern "C" void kernel_launch(void* const* d_in, const int* in_sizes, int n_in,
                              void* d_out, int out_size)
{
    const float* uv = (const float*)d_in[0];   // [N,2] fp32
    const float* kv = (const float*)d_in[1];   // k_vector [5]
    const float* fx = (const float*)d_in[2];
    const float* fy = (const float*)d_in[3];

    int n       = in_sizes[0] / 2;
    int n_pairs = n / 2;
    int n_tail  = n - 2 * n_pairs;

    const int T = PBLOCKS * PTHREADS;          // 303104 threads
    const int ITERS = 7;                       // bench: 2^21 pairs -> 6.92/thread

    if (n_tail == 0 && n_pairs > (long)(ITERS - 1) * T
                    && n_pairs <= (long)ITERS * T) {
        kb_persist_kernel<ITERS><<<PBLOCKS, PTHREADS>>>(
            (const float4*)uv, kv, fx, fy, (float4*)d_out, n_pairs);
    } else {
        const int threads = 256;
        int blocks = 148 * 8;
        int need   = (n_pairs + threads - 1) / threads;
        if (need < blocks) blocks = need > 0 ? need : 1;
        kb_generic_kernel<<<blocks, threads>>>(
            (const float4*)uv, (const float2*)uv, kv, fx, fy,
            (float4*)d_out, (float2*)d_out, n_pairs, n_tail);
    }
}

// round 14
// speedup vs baseline: 1.0269x; 1.0269x over previous
#include <cuda_runtime.h>

// Kannala-Brandt fisheye round-trip — memory-floor form.
//
// The task moves 67MB (fp32 in/out, irreducible) and the R3-R13 record shows
// duration pinned at the effective streaming rate; compute is trimmed to the
// minimum that preserves rel_err << 1e-3:
//
//   ru = |(px-cx)/fx, (py-cy)/fy|        (sqrt via MUFU.RSQ: ru = q*rsqrt(q))
//   ONE closed-form fixed-point step:  t = ru * (2 - d(ru))
//       e1 <= e0*|1-f'| <= 0.0102*0.013 = 1.3e-4 in t -> <=2.6e-5 rel in output
//   out = sinc(t)*(pixel-center) + center      (focal lengths cancel;
//       d(t)*sin(t)/ru == sin(t)/t at the fixed point)
//   sinc = deg-6 Taylor in t^2 (trunc 3.0e-5 abs at t=1.35)
//   combined worst-corner error ~8e-5 vs 1e-3 tolerance.
//
// Structure = R12 winner: 2048 blocks x 256 thr, 4 front-batched LDG.128 per
// thread, compile-time-checked exact division, zero bounds checks.

#define CX 640.0f
#define CY 480.0f

#define XTHREADS 256

struct KParams { float k0, k1, k2, k3, k4, rfx, rfy; };

__device__ __forceinline__ KParams load_params(const float* kvec,
                                               const float* fx_p,
                                               const float* fy_p)
{
    KParams P;
    P.k0 = __ldg(&kvec[0]); P.k1 = __ldg(&kvec[1]); P.k2 = __ldg(&kvec[2]);
    P.k3 = __ldg(&kvec[3]); P.k4 = __ldg(&kvec[4]);
    P.rfx = __fdividef(1.0f, __ldg(fx_p));
    P.rfy = __fdividef(1.0f, __ldg(fy_p));
    return P;
}

__device__ __forceinline__ float2 kb_point(float px, float py, const KParams& P)
{
    float dx = px - CX;
    float dy = py - CY;
    float mx = dx * P.rfx;
    float my = dy * P.rfy;
    float q  = fmaf(mx, mx, fmaf(my, my, 1e-30f));
    float ru = q * rsqrtf(q);                       // sqrt(q)

    // one closed-form fixed-point step: t = ru * (2 - d(ru))
    float d = ((((P.k4 * ru + P.k3) * ru + P.k2) * ru + P.k1) * ru + P.k0);
    float t = ru * (2.0f - d);

    // w = sinc(t), deg-6 Taylor in t^2
    float t2 = t * t;
    float w = fmaf(t2, fmaf(t2, fmaf(t2, -1.9841270e-4f, 8.3333333e-3f),
                            -1.6666667e-1f), 1.0f);

    return make_float2(fmaf(w, dx, CX), fmaf(w, dy, CY));
}

// ---- specialized: n_pairs == gridDim.x * XTHREADS * ITERS exactly ----
template <int ITERS>
__global__ void __launch_bounds__(XTHREADS)
kb_exact_kernel(const float4* __restrict__ in4,
                const float*  __restrict__ kvec,
                const float*  __restrict__ fx_p,
                const float*  __restrict__ fy_p,
                float4*       __restrict__ out4)
{
    const int stride = gridDim.x * XTHREADS;
    const int base   = blockIdx.x * XTHREADS + threadIdx.x;
    const KParams P  = load_params(kvec, fx_p, fy_p);

    float4 v[ITERS];
#pragma unroll
    for (int k = 0; k < ITERS; ++k)
        v[k] = in4[base + k * stride];              // ITERS independent LDG.128

#pragma unroll
    for (int k = 0; k < ITERS; ++k) {
        float2 a = kb_point(v[k].x, v[k].y, P);
        float2 b = kb_point(v[k].z, v[k].w, P);
        out4[base + k * stride] = make_float4(a.x, a.y, b.x, b.y);
    }
}

// ---- generic fallback ----
__global__ void __launch_bounds__(256)
kb_generic_kernel(const float4* __restrict__ in4,
                  const float2* __restrict__ in2,
                  const float*  __restrict__ kvec,
                  const float*  __restrict__ fx_p,
                  const float*  __restrict__ fy_p,
                  float4*       __restrict__ out4,
                  float2*       __restrict__ out2,
                  int n_pairs, int n_tail_pts)
{
    const int stride = gridDim.x * blockDim.x;
    int i = blockIdx.x * blockDim.x + threadIdx.x;
    const KParams P = load_params(kvec, fx_p, fy_p);

    for (; i < n_pairs; i += stride) {
        float4 p = in4[i];
        float2 a = kb_point(p.x, p.y, P);
        float2 b = kb_point(p.z, p.w, P);
        out4[i] = make_float4(a.x, a.y, b.x, b.y);
    }

    if (n_tail_pts && blockIdx.x == 0 && threadIdx.x == 0) {
        for (int j = 0; j < n_tail_pts; ++j) {
            int idx = 2 * n_pairs + j;
            float2 p = in2[idx];
            out2[idx] = kb_point(p.x, p.y, P);
        }
    }
}

extern "C" void kernel_launch(void* const* d_in, const int* in_sizes, int n_in,
                              void* d_out, int out_size)
{
    const float* uv = (const float*)d_in[0];   // [N,2] fp32
    const float* kv = (const float*)d_in[1];   // k_vector [5]
    const float* fx = (const float*)d_in[2];
    const float* fy = (const float*)d_in[3];

    int n       = in_sizes[0] / 2;
    int n_pairs = n / 2;
    int n_tail  = n - 2 * n_pairs;

    const int ITERS = 4;
    if (n_tail == 0 && n_pairs % (XTHREADS * ITERS) == 0) {
        // bench shape: N = 4194304 -> n_pairs = 2^21 = 2048 * 256 * 4
        int blocks = n_pairs / (XTHREADS * ITERS);
        kb_exact_kernel<ITERS><<<blocks, XTHREADS>>>(
            (const float4*)uv, kv, fx, fy, (float4*)d_out);
    } else {
        const int threads = 256;
        int blocks = 148 * 8;
        int need   = (n_pairs + threads - 1) / threads;
        if (need < blocks) blocks = need > 0 ? need : 1;
        kb_generic_kernel<<<blocks, threads>>>(
            (const float4*)uv, (const float2*)uv, kv, fx, fy,
            (float4*)d_out, (float2*)d_out, n_pairs, n_tail);
    }
}

// round 15
// speedup vs baseline: 1.0299x; 1.0030x over previous
#include <cuda_runtime.h>

// Kannala-Brandt fisheye round-trip — converged, memory-floor kernel.
//
// The task streams 67MB (fp32 [N,2] in and out, irreducible). Measured
// 10.7us = 6.26 TB/s = the B300 LTS chip cap; R12/R14 showed duration is
// invariant to compute (fma 21-28%, issue 43-56% — all slack). So compute
// uses the higher-accuracy validated math for free:
//
//   ru = |(px-cx)/fx, (py-cy)/fy|      (sqrt via MUFU.RSQ: ru = q*rsqrt(q))
//   t:  2 fixed-point steps of t <- t - (t*d(t) - ru)
//       (contraction |1-f'| <= 0.013 -> e2 ~ 1.2e-6)
//   out = sinc(t)*(pixel-center) + center   (deg-8 Taylor sinc;
//        d(t)*sin(t)/ru == sin(t)/t at the fixed point, focal lengths cancel)
//   rel_err ~ 6.2e-6 vs 1e-3 tolerance.
//
// Structure: exact-division specialization, ITERS=2 x 4096 blocks x 256 thr —
// finest CTA granularity with dual front-batched LDG.128, zero bounds checks.

#define CX 640.0f
#define CY 480.0f

#define XTHREADS 256

struct KParams { float k0, k1, k2, k3, k4, rfx, rfy; };

__device__ __forceinline__ KParams load_params(const float* kvec,
                                               const float* fx_p,
                                               const float* fy_p)
{
    KParams P;
    P.k0 = __ldg(&kvec[0]); P.k1 = __ldg(&kvec[1]); P.k2 = __ldg(&kvec[2]);
    P.k3 = __ldg(&kvec[3]); P.k4 = __ldg(&kvec[4]);
    P.rfx = __fdividef(1.0f, __ldg(fx_p));
    P.rfy = __fdividef(1.0f, __ldg(fy_p));
    return P;
}

__device__ __forceinline__ float2 kb_point(float px, float py, const KParams& P)
{
    float dx = px - CX;
    float dy = py - CY;
    float mx = dx * P.rfx;
    float my = dy * P.rfy;
    float q  = fmaf(mx, mx, fmaf(my, my, 1e-30f));
    float ru = q * rsqrtf(q);                       // sqrt(q)

    // 2 fixed-point steps on t*d(t) = ru
    float t = ru;
#pragma unroll
    for (int it = 0; it < 2; ++it) {
        float p = ((((P.k4 * t + P.k3) * t + P.k2) * t + P.k1) * t + P.k0);
        float r = fmaf(p, t, -ru);
        t = t - r;
    }

    // w = sinc(t), deg-8 Taylor in t^2
    float t2 = t * t;
    float w = fmaf(t2, fmaf(t2, fmaf(t2, fmaf(t2, 2.7557319e-6f, -1.9841270e-4f),
                                     8.3333333e-3f), -1.6666667e-1f), 1.0f);

    return make_float2(fmaf(w, dx, CX), fmaf(w, dy, CY));
}

// ---- specialized: n_pairs == gridDim.x * XTHREADS * ITERS exactly ----
template <int ITERS>
__global__ void __launch_bounds__(XTHREADS)
kb_exact_kernel(const float4* __restrict__ in4,
                const float*  __restrict__ kvec,
                const float*  __restrict__ fx_p,
                const float*  __restrict__ fy_p,
                float4*       __restrict__ out4)
{
    const int stride = gridDim.x * XTHREADS;
    const int base   = blockIdx.x * XTHREADS + threadIdx.x;
    const KParams P  = load_params(kvec, fx_p, fy_p);

    float4 v[ITERS];
#pragma unroll
    for (int k = 0; k < ITERS; ++k)
        v[k] = in4[base + k * stride];              // ITERS independent LDG.128

#pragma unroll
    for (int k = 0; k < ITERS; ++k) {
        float2 a = kb_point(v[k].x, v[k].y, P);
        float2 b = kb_point(v[k].z, v[k].w, P);
        out4[base + k * stride] = make_float4(a.x, a.y, b.x, b.y);
    }
}

// ---- generic fallback ----
__global__ void __launch_bounds__(256)
kb_generic_kernel(const float4* __restrict__ in4,
                  const float2* __restrict__ in2,
                  const float*  __restrict__ kvec,
                  const float*  __restrict__ fx_p,
                  const float*  __restrict__ fy_p,
                  float4*       __restrict__ out4,
                  float2*       __restrict__ out2,
                  int n_pairs, int n_tail_pts)
{
    const int stride = gridDim.x * blockDim.x;
    int i = blockIdx.x * blockDim.x + threadIdx.x;
    const KParams P = load_params(kvec, fx_p, fy_p);

    for (; i < n_pairs; i += stride) {
        float4 p = in4[i];
        float2 a = kb_point(p.x, p.y, P);
        float2 b = kb_point(p.z, p.w, P);
        out4[i] = make_float4(a.x, a.y, b.x, b.y);
    }

    if (n_tail_pts && blockIdx.x == 0 && threadIdx.x == 0) {
        for (int j = 0; j < n_tail_pts; ++j) {
            int idx = 2 * n_pairs + j;
            float2 p = in2[idx];
            out2[idx] = kb_point(p.x, p.y, P);
        }
    }
}

extern "C" void kernel_launch(void* const* d_in, const int* in_sizes, int n_in,
                              void* d_out, int out_size)
{
    const float* uv = (const float*)d_in[0];   // [N,2] fp32
    const float* kv = (const float*)d_in[1];   // k_vector [5]
    const float* fx = (const float*)d_in[2];
    const float* fy = (const float*)d_in[3];

    int n       = in_sizes[0] / 2;
    int n_pairs = n / 2;
    int n_tail  = n - 2 * n_pairs;

    const int ITERS = 2;
    if (n_tail == 0 && n_pairs % (XTHREADS * ITERS) == 0) {
        // bench shape: N = 4194304 -> n_pairs = 2^21 = 4096 * 256 * 2
        int blocks = n_pairs / (XTHREADS * ITERS);
        kb_exact_kernel<ITERS><<<blocks, XTHREADS>>>(
            (const float4*)uv, kv, fx, fy, (float4*)d_out);
    } else {
        const int threads = 256;
        int blocks = 148 * 8;
        int need   = (n_pairs + threads - 1) / threads;
        if (need < blocks) blocks = need > 0 ? need : 1;
        kb_generic_kernel<<<blocks, threads>>>(
            (const float4*)uv, (const float2*)uv, kv, fx, fy,
            (float4*)d_out, (float2*)d_out, n_pairs, n_tail);
    }
}